// round 1
// baseline (speedup 1.0000x reference)
#include <cuda_runtime.h>
#include <math.h>

#define DMODEL 1024
#define NHEAD  16
#define DHEAD  64
#define FFDIM  4096
#define ROWS   4096      // B*S
#define SEQ    2048
#define LN_EPS 1e-6f

// ---------------- scratch (no allocation allowed) ----------------
__device__ float g_ln [ROWS * DMODEL];
__device__ float g_q  [ROWS * DMODEL];
__device__ float g_k  [ROWS * DMODEL];
__device__ float g_v  [ROWS * DMODEL];
__device__ float g_att[ROWS * DMODEL];
__device__ float g_x1 [ROWS * DMODEL];
__device__ float g_ff [ROWS * FFDIM];

// ---------------- LayerNorm (torch semantics: ddof=1, std+eps) ----------------
__global__ void ln_kernel(const float* __restrict__ x,
                          const float* __restrict__ gamma,
                          const float* __restrict__ beta,
                          float* __restrict__ out) {
    int row = blockIdx.x;
    int t = threadIdx.x;                      // 256 threads, 4 floats each
    const float4* xr = (const float4*)(x + (size_t)row * DMODEL);
    float4 v = xr[t];
    float s  = v.x + v.y + v.z + v.w;
    float ss = v.x * v.x + v.y * v.y + v.z * v.z + v.w * v.w;
    #pragma unroll
    for (int o = 16; o > 0; o >>= 1) {
        s  += __shfl_xor_sync(0xFFFFFFFFu, s,  o);
        ss += __shfl_xor_sync(0xFFFFFFFFu, ss, o);
    }
    __shared__ float rs[8], rss[8];
    int wid = t >> 5, lid = t & 31;
    if (lid == 0) { rs[wid] = s; rss[wid] = ss; }
    __syncthreads();
    s = 0.f; ss = 0.f;
    #pragma unroll
    for (int i = 0; i < 8; i++) { s += rs[i]; ss += rss[i]; }
    float mean = s * (1.0f / DMODEL);
    float var  = (ss - (float)DMODEL * mean * mean) * (1.0f / (DMODEL - 1));
    float inv  = 1.0f / (sqrtf(fmaxf(var, 0.0f)) + LN_EPS);
    const float4 gg = ((const float4*)gamma)[t];
    const float4 bb = ((const float4*)beta)[t];
    float4 o;
    o.x = gg.x * (v.x - mean) * inv + bb.x;
    o.y = gg.y * (v.y - mean) * inv + bb.y;
    o.z = gg.z * (v.z - mean) * inv + bb.z;
    o.w = gg.w * (v.w - mean) * inv + bb.w;
    ((float4*)(out + (size_t)row * DMODEL))[t] = o;
}

// ---------------- Generic fp32 GEMM: C = act(A@B + bias) + res ----------------
// A: [M,K] row-major, B: [K,N] row-major. 64x64 tile, BK=16, 256 thr, 4x4 micro.
template<bool RELU>
__global__ void gemm_kernel(const float* __restrict__ A,
                            const float* __restrict__ B,
                            const float* __restrict__ bias,   // [N] or null
                            const float* __restrict__ res,    // [M,N] or null
                            float* __restrict__ C,
                            int M, int N, int K) {
    __shared__ float As[16][65];   // transposed A tile [k][m], padded
    __shared__ float Bs[16][64];   // natural B tile [k][n]
    int tid = threadIdx.x;
    int ty = tid >> 4, tx = tid & 15;
    int row0 = blockIdx.y * 64, col0 = blockIdx.x * 64;

    int ar = tid >> 2;             // 0..63 : A tile row
    int ac = (tid & 3) * 4;        // 0,4,8,12 : A tile k-chunk
    int br = tid >> 4;             // 0..15 : B tile k
    int bc = (tid & 15) * 4;       // B tile col chunk

    const float* Aptr = A + (size_t)(row0 + ar) * K + ac;

    float acc[4][4];
    #pragma unroll
    for (int i = 0; i < 4; i++)
        #pragma unroll
        for (int j = 0; j < 4; j++) acc[i][j] = 0.0f;

    for (int k0 = 0; k0 < K; k0 += 16) {
        float4 av = *(const float4*)(Aptr + k0);
        float4 bv = *(const float4*)(B + (size_t)(k0 + br) * N + col0 + bc);
        As[ac + 0][ar] = av.x;
        As[ac + 1][ar] = av.y;
        As[ac + 2][ar] = av.z;
        As[ac + 3][ar] = av.w;
        *(float4*)&Bs[br][bc] = bv;
        __syncthreads();
        #pragma unroll
        for (int k = 0; k < 16; k++) {
            float a0 = As[k][ty * 4 + 0];
            float a1 = As[k][ty * 4 + 1];
            float a2 = As[k][ty * 4 + 2];
            float a3 = As[k][ty * 4 + 3];
            float4 b4 = *(const float4*)&Bs[k][tx * 4];
            acc[0][0] += a0 * b4.x; acc[0][1] += a0 * b4.y; acc[0][2] += a0 * b4.z; acc[0][3] += a0 * b4.w;
            acc[1][0] += a1 * b4.x; acc[1][1] += a1 * b4.y; acc[1][2] += a1 * b4.z; acc[1][3] += a1 * b4.w;
            acc[2][0] += a2 * b4.x; acc[2][1] += a2 * b4.y; acc[2][2] += a2 * b4.z; acc[2][3] += a2 * b4.w;
            acc[3][0] += a3 * b4.x; acc[3][1] += a3 * b4.y; acc[3][2] += a3 * b4.z; acc[3][3] += a3 * b4.w;
        }
        __syncthreads();
    }

    int c = col0 + tx * 4;
    float4 bias4 = make_float4(0.f, 0.f, 0.f, 0.f);
    if (bias) bias4 = *(const float4*)(bias + c);
    #pragma unroll
    for (int i = 0; i < 4; i++) {
        int r = row0 + ty * 4 + i;
        float4 val;
        val.x = acc[i][0] + bias4.x;
        val.y = acc[i][1] + bias4.y;
        val.z = acc[i][2] + bias4.z;
        val.w = acc[i][3] + bias4.w;
        if (RELU) {
            val.x = fmaxf(val.x, 0.f); val.y = fmaxf(val.y, 0.f);
            val.z = fmaxf(val.z, 0.f); val.w = fmaxf(val.w, 0.f);
        }
        if (res) {
            float4 rv = *(const float4*)(res + (size_t)r * N + c);
            val.x += rv.x; val.y += rv.y; val.z += rv.z; val.w += rv.w;
        }
        *(float4*)(C + (size_t)r * N + c) = val;
    }
}

// ---------------- Flash attention (fp32), 64-query tile per (b,h) ----------------
// Q/K/V: [ROWS, DMODEL] with head h occupying cols [h*64, h*64+64)
__global__ void attn_kernel(const float* __restrict__ Q,
                            const float* __restrict__ Kg,
                            const float* __restrict__ Vg,
                            float* __restrict__ O) {
    extern __shared__ float sm[];
    float* Qt = sm;                  // [64][65] : Qt[d*65 + q], pre-scaled by 1/8
    float* Kt = sm + 4160;           // [64][65] : Kt[d*65 + k]
    float* Vs = sm + 8320;           // [64][64] : Vs[k*64 + d]
    float* Ss = sm + 12416;          // [64][65] : Ss[q*65 + k]  (P after softmax)

    int b = blockIdx.z, h = blockIdx.y, qt = blockIdx.x;
    int tid = threadIdx.x;
    int ty = tid >> 4, tx = tid & 15;

    int lr = tid >> 2;        // 0..63 : tile row for loads
    int c0 = tid & 3;         // chunk phase

    // load Q tile (transposed, pre-scaled by 1/sqrt(DH)=0.125)
    {
        size_t grow = (size_t)(b * SEQ + qt * 64 + lr) * DMODEL + h * 64;
        #pragma unroll
        for (int i = 0; i < 4; i++) {
            int cch = c0 + 4 * i;            // 0..15
            float4 v = *(const float4*)(Q + grow + cch * 4);
            Qt[(cch * 4 + 0) * 65 + lr] = v.x * 0.125f;
            Qt[(cch * 4 + 1) * 65 + lr] = v.y * 0.125f;
            Qt[(cch * 4 + 2) * 65 + lr] = v.z * 0.125f;
            Qt[(cch * 4 + 3) * 65 + lr] = v.w * 0.125f;
        }
    }

    float m_i[4], l_i[4], o_acc[4][4];
    #pragma unroll
    for (int i = 0; i < 4; i++) {
        m_i[i] = -1e30f; l_i[i] = 0.f;
        #pragma unroll
        for (int j = 0; j < 4; j++) o_acc[i][j] = 0.f;
    }

    for (int kt = 0; kt < SEQ / 64; kt++) {
        __syncthreads();   // previous PV done (and Qt ready on first iter)
        // load K (transposed) and V (natural) tiles
        {
            size_t grow = (size_t)(b * SEQ + kt * 64 + lr) * DMODEL + h * 64;
            #pragma unroll
            for (int i = 0; i < 4; i++) {
                int cch = c0 + 4 * i;
                float4 kv = *(const float4*)(Kg + grow + cch * 4);
                Kt[(cch * 4 + 0) * 65 + lr] = kv.x;
                Kt[(cch * 4 + 1) * 65 + lr] = kv.y;
                Kt[(cch * 4 + 2) * 65 + lr] = kv.z;
                Kt[(cch * 4 + 3) * 65 + lr] = kv.w;
                float4 vv = *(const float4*)(Vg + grow + cch * 4);
                *(float4*)&Vs[lr * 64 + cch * 4] = vv;
            }
        }
        __syncthreads();

        // S = (Q/8) @ K^T   (64x64, 4x4 per thread)
        float s[4][4];
        #pragma unroll
        for (int i = 0; i < 4; i++)
            #pragma unroll
            for (int j = 0; j < 4; j++) s[i][j] = 0.f;
        #pragma unroll 8
        for (int d = 0; d < 64; d++) {
            float qr[4], kr[4];
            #pragma unroll
            for (int i = 0; i < 4; i++) qr[i] = Qt[d * 65 + ty * 4 + i];
            #pragma unroll
            for (int j = 0; j < 4; j++) kr[j] = Kt[d * 65 + tx * 4 + j];
            #pragma unroll
            for (int i = 0; i < 4; i++)
                #pragma unroll
                for (int j = 0; j < 4; j++) s[i][j] += qr[i] * kr[j];
        }

        // online softmax: each q-row spans the 16 lanes sharing ty (half-warp)
        #pragma unroll
        for (int i = 0; i < 4; i++) {
            float rm = fmaxf(fmaxf(s[i][0], s[i][1]), fmaxf(s[i][2], s[i][3]));
            #pragma unroll
            for (int o = 8; o >= 1; o >>= 1)
                rm = fmaxf(rm, __shfl_xor_sync(0xFFFFFFFFu, rm, o));
            float mnew  = fmaxf(m_i[i], rm);
            float alpha = __expf(m_i[i] - mnew);
            m_i[i] = mnew;
            float rsum = 0.f;
            #pragma unroll
            for (int j = 0; j < 4; j++) {
                s[i][j] = __expf(s[i][j] - mnew);
                rsum += s[i][j];
            }
            #pragma unroll
            for (int o = 8; o >= 1; o >>= 1)
                rsum += __shfl_xor_sync(0xFFFFFFFFu, rsum, o);
            l_i[i] = l_i[i] * alpha + rsum;
            #pragma unroll
            for (int j = 0; j < 4; j++) o_acc[i][j] *= alpha;
            // stage P
            #pragma unroll
            for (int j = 0; j < 4; j++)
                Ss[(ty * 4 + i) * 65 + tx * 4 + j] = s[i][j];
        }
        __syncthreads();

        // O += P @ V
        #pragma unroll 8
        for (int kk = 0; kk < 64; kk++) {
            float4 vv = *(const float4*)&Vs[kk * 64 + tx * 4];
            float p[4];
            #pragma unroll
            for (int i = 0; i < 4; i++) p[i] = Ss[(ty * 4 + i) * 65 + kk];
            #pragma unroll
            for (int i = 0; i < 4; i++) {
                o_acc[i][0] += p[i] * vv.x;
                o_acc[i][1] += p[i] * vv.y;
                o_acc[i][2] += p[i] * vv.z;
                o_acc[i][3] += p[i] * vv.w;
            }
        }
    }

    // epilogue: O / l  -> [B,S,H,DH] packed as [ROWS, DMODEL]
    #pragma unroll
    for (int i = 0; i < 4; i++) {
        float inv = 1.0f / l_i[i];
        float4 val;
        val.x = o_acc[i][0] * inv;
        val.y = o_acc[i][1] * inv;
        val.z = o_acc[i][2] * inv;
        val.w = o_acc[i][3] * inv;
        size_t idx = (size_t)(b * SEQ + qt * 64 + ty * 4 + i) * DMODEL + h * 64 + tx * 4;
        *(float4*)(O + idx) = val;
    }
}

// ---------------- launch ----------------
extern "C" void kernel_launch(void* const* d_in, const int* in_sizes, int n_in,
                              void* d_out, int out_size) {
    const float* x   = (const float*)d_in[0];
    const float* w_q = (const float*)d_in[1];
    const float* w_k = (const float*)d_in[2];
    const float* w_v = (const float*)d_in[3];
    const float* w_o = (const float*)d_in[4];
    const float* w1  = (const float*)d_in[5];
    const float* b1  = (const float*)d_in[6];
    const float* w2  = (const float*)d_in[7];
    const float* b2  = (const float*)d_in[8];
    const float* g1  = (const float*)d_in[9];
    const float* be1 = (const float*)d_in[10];
    const float* g2  = (const float*)d_in[11];
    const float* be2 = (const float*)d_in[12];
    float* out = (float*)d_out;

    float *ln, *q, *k, *v, *att, *x1, *ff;
    cudaGetSymbolAddress((void**)&ln,  g_ln);
    cudaGetSymbolAddress((void**)&q,   g_q);
    cudaGetSymbolAddress((void**)&k,   g_k);
    cudaGetSymbolAddress((void**)&v,   g_v);
    cudaGetSymbolAddress((void**)&att, g_att);
    cudaGetSymbolAddress((void**)&x1,  g_x1);
    cudaGetSymbolAddress((void**)&ff,  g_ff);

    const int attn_smem = (4160 * 3 + 4096) * (int)sizeof(float);  // 66304 B
    cudaFuncSetAttribute(attn_kernel, cudaFuncAttributeMaxDynamicSharedMemorySize, attn_smem);

    // LN1
    ln_kernel<<<ROWS, 256>>>(x, g1, be1, ln);
    // QKV projections
    gemm_kernel<false><<<dim3(DMODEL / 64, ROWS / 64), 256>>>(ln, w_q, nullptr, nullptr, q, ROWS, DMODEL, DMODEL);
    gemm_kernel<false><<<dim3(DMODEL / 64, ROWS / 64), 256>>>(ln, w_k, nullptr, nullptr, k, ROWS, DMODEL, DMODEL);
    gemm_kernel<false><<<dim3(DMODEL / 64, ROWS / 64), 256>>>(ln, w_v, nullptr, nullptr, v, ROWS, DMODEL, DMODEL);
    // attention
    attn_kernel<<<dim3(SEQ / 64, NHEAD, 2), 256, attn_smem>>>(q, k, v, att);
    // output projection + residual
    gemm_kernel<false><<<dim3(DMODEL / 64, ROWS / 64), 256>>>(att, w_o, nullptr, x, x1, ROWS, DMODEL, DMODEL);
    // LN2
    ln_kernel<<<ROWS, 256>>>(x1, g2, be2, ln);
    // FFN
    gemm_kernel<true ><<<dim3(FFDIM / 64, ROWS / 64), 256>>>(ln, w1, b1, nullptr, ff, ROWS, FFDIM, DMODEL);
    gemm_kernel<false><<<dim3(DMODEL / 64, ROWS / 64), 256>>>(ff, w2, b2, x1, out, ROWS, DMODEL, FFDIM);
}

// round 2
// speedup vs baseline: 1.1038x; 1.1038x over previous
#include <cuda_runtime.h>
#include <cuda_bf16.h>
#include <math.h>

#define DMODEL 1024
#define NHEAD  16
#define DHEAD  64
#define FFDIM  4096
#define ROWS   4096      // B*S
#define SEQ    2048
#define LN_EPS 1e-6f

// ---------------- scratch (no allocation allowed) ----------------
__device__ float g_ln [ROWS * DMODEL];
__device__ float g_q  [ROWS * DMODEL];
__device__ float g_k  [ROWS * DMODEL];
__device__ float g_v  [ROWS * DMODEL];
__device__ float g_att[ROWS * DMODEL];
__device__ float g_x1 [ROWS * DMODEL];
__device__ float g_ff [ROWS * FFDIM];

// ---------------- LayerNorm (torch semantics: ddof=1, std+eps) ----------------
__global__ void ln_kernel(const float* __restrict__ x,
                          const float* __restrict__ gamma,
                          const float* __restrict__ beta,
                          float* __restrict__ out) {
    int row = blockIdx.x;
    int t = threadIdx.x;                      // 256 threads, 4 floats each
    const float4* xr = (const float4*)(x + (size_t)row * DMODEL);
    float4 v = xr[t];
    float s  = v.x + v.y + v.z + v.w;
    float ss = v.x * v.x + v.y * v.y + v.z * v.z + v.w * v.w;
    #pragma unroll
    for (int o = 16; o > 0; o >>= 1) {
        s  += __shfl_xor_sync(0xFFFFFFFFu, s,  o);
        ss += __shfl_xor_sync(0xFFFFFFFFu, ss, o);
    }
    __shared__ float rs[8], rss[8];
    int wid = t >> 5, lid = t & 31;
    if (lid == 0) { rs[wid] = s; rss[wid] = ss; }
    __syncthreads();
    s = 0.f; ss = 0.f;
    #pragma unroll
    for (int i = 0; i < 8; i++) { s += rs[i]; ss += rss[i]; }
    float mean = s * (1.0f / DMODEL);
    float var  = (ss - (float)DMODEL * mean * mean) * (1.0f / (DMODEL - 1));
    float inv  = 1.0f / (sqrtf(fmaxf(var, 0.0f)) + LN_EPS);
    const float4 gg = ((const float4*)gamma)[t];
    const float4 bb = ((const float4*)beta)[t];
    float4 o;
    o.x = gg.x * (v.x - mean) * inv + bb.x;
    o.y = gg.y * (v.y - mean) * inv + bb.y;
    o.z = gg.z * (v.z - mean) * inv + bb.z;
    o.w = gg.w * (v.w - mean) * inv + bb.w;
    ((float4*)(out + (size_t)row * DMODEL))[t] = o;
}

// ---------------- Tensor-core GEMM (bf16 split, 3-product compensation) ----------
// C = act(A@B + bias) + res.  A:[M,K] rm, B:[K,N] rm, fp32 in/out.
// Block tile 128x128, BK=32. 256 threads = 8 warps (2m x 4n), warp tile 64x32.
// mma.sync.m16n8k16 bf16: C = Ah*Bh + Ah*Bl + Al*Bh (fp32 accum).
#define BM 128
#define BN 128
#define BK 32
#define SKP 40   // smem row stride in halves (pad 8) -> conflict-free frags

__device__ __forceinline__ void mma16816(float c[4], const unsigned a[4], const unsigned b[2]) {
    asm volatile(
        "mma.sync.aligned.m16n8k16.row.col.f32.bf16.bf16.f32 "
        "{%0,%1,%2,%3}, {%4,%5,%6,%7}, {%8,%9}, {%0,%1,%2,%3};\n"
        : "+f"(c[0]), "+f"(c[1]), "+f"(c[2]), "+f"(c[3])
        : "r"(a[0]), "r"(a[1]), "r"(a[2]), "r"(a[3]), "r"(b[0]), "r"(b[1]));
}

template<bool RELU>
__global__ __launch_bounds__(256, 1)
void gemm_bf16s_kernel(const float* __restrict__ A,
                       const float* __restrict__ B,
                       const float* __restrict__ bias,   // [N] or null
                       const float* __restrict__ res,    // [M,N] or null
                       float* __restrict__ C,
                       int M, int N, int K) {
    __shared__ __nv_bfloat16 Ah[BM * SKP], Al[BM * SKP];
    __shared__ __nv_bfloat16 Bh[BN * SKP], Bl[BN * SKP];   // stored [n][k]

    int tid  = threadIdx.x;
    int lane = tid & 31;
    int warp = tid >> 5;
    int g   = lane >> 2;        // group 0..7
    int tig = lane & 3;         // thread-in-group
    int wm = warp & 1;          // 0..1
    int wn = warp >> 1;         // 0..3
    int m_base = wm * 64;
    int n_base = wn * 32;
    int row0 = blockIdx.y * BM, col0 = blockIdx.x * BN;

    float acc[4][4][4];
    #pragma unroll
    for (int mi = 0; mi < 4; mi++)
        #pragma unroll
        for (int ni = 0; ni < 4; ni++)
            #pragma unroll
            for (int r = 0; r < 4; r++) acc[mi][ni][r] = 0.0f;

    for (int k0 = 0; k0 < K; k0 += BK) {
        // ---- fill A tile (BM x BK) from [M][K]; convert to hi/lo bf16 ----
        #pragma unroll
        for (int i = 0; i < 4; i++) {
            int idx = tid + 256 * i;          // 1024 float4 slots
            int r = idx >> 3;                 // 0..127
            int c4 = (idx & 7) * 4;           // 0..28
            float4 v = *(const float4*)(A + (size_t)(row0 + r) * K + k0 + c4);
            #pragma unroll
            for (int j = 0; j < 4; j++) {
                float f = (&v.x)[j];
                __nv_bfloat16 hi = __float2bfloat16_rn(f);
                __nv_bfloat16 lo = __float2bfloat16_rn(f - __bfloat162float(hi));
                Ah[r * SKP + c4 + j] = hi;
                Al[r * SKP + c4 + j] = lo;
            }
        }
        // ---- fill B tile (BK x BN) from [K][N], transpose into [n][k] ----
        #pragma unroll
        for (int i = 0; i < 8; i++) {
            int idx = tid + 256 * i;          // 2048 float2 slots
            int kk = idx >> 6;                // 0..31
            int n2 = (idx & 63) * 2;          // 0..126
            float2 v = *(const float2*)(B + (size_t)(k0 + kk) * N + col0 + n2);
            #pragma unroll
            for (int j = 0; j < 2; j++) {
                float f = (&v.x)[j];
                __nv_bfloat16 hi = __float2bfloat16_rn(f);
                __nv_bfloat16 lo = __float2bfloat16_rn(f - __bfloat162float(hi));
                Bh[(n2 + j) * SKP + kk] = hi;
                Bl[(n2 + j) * SKP + kk] = lo;
            }
        }
        __syncthreads();

        #pragma unroll
        for (int ks = 0; ks < 2; ks++) {
            int kk = ks * 16;
            unsigned a_h[4][4], a_l[4][4], b_h[4][2], b_l[4][2];
            #pragma unroll
            for (int mi = 0; mi < 4; mi++) {
                int r = m_base + mi * 16 + g;
                int base = r * SKP + kk + 2 * tig;
                a_h[mi][0] = *(const unsigned*)(Ah + base);
                a_h[mi][1] = *(const unsigned*)(Ah + base + 8 * SKP);
                a_h[mi][2] = *(const unsigned*)(Ah + base + 8);
                a_h[mi][3] = *(const unsigned*)(Ah + base + 8 * SKP + 8);
                a_l[mi][0] = *(const unsigned*)(Al + base);
                a_l[mi][1] = *(const unsigned*)(Al + base + 8 * SKP);
                a_l[mi][2] = *(const unsigned*)(Al + base + 8);
                a_l[mi][3] = *(const unsigned*)(Al + base + 8 * SKP + 8);
            }
            #pragma unroll
            for (int ni = 0; ni < 4; ni++) {
                int n = n_base + ni * 8 + g;
                int base = n * SKP + kk + 2 * tig;
                b_h[ni][0] = *(const unsigned*)(Bh + base);
                b_h[ni][1] = *(const unsigned*)(Bh + base + 8);
                b_l[ni][0] = *(const unsigned*)(Bl + base);
                b_l[ni][1] = *(const unsigned*)(Bl + base + 8);
            }
            #pragma unroll
            for (int mi = 0; mi < 4; mi++)
                #pragma unroll
                for (int ni = 0; ni < 4; ni++) {
                    mma16816(acc[mi][ni], a_h[mi], b_h[ni]);
                    mma16816(acc[mi][ni], a_h[mi], b_l[ni]);
                    mma16816(acc[mi][ni], a_l[mi], b_h[ni]);
                }
        }
        __syncthreads();
    }

    // ---- epilogue ----
    #pragma unroll
    for (int mi = 0; mi < 4; mi++) {
        #pragma unroll
        for (int ni = 0; ni < 4; ni++) {
            int r  = row0 + m_base + mi * 16 + g;
            int c  = col0 + n_base + ni * 8 + 2 * tig;
            float2 b2 = make_float2(0.f, 0.f);
            if (bias) b2 = *(const float2*)(bias + c);
            float2 v0, v1;
            v0.x = acc[mi][ni][0] + b2.x; v0.y = acc[mi][ni][1] + b2.y;
            v1.x = acc[mi][ni][2] + b2.x; v1.y = acc[mi][ni][3] + b2.y;
            if (RELU) {
                v0.x = fmaxf(v0.x, 0.f); v0.y = fmaxf(v0.y, 0.f);
                v1.x = fmaxf(v1.x, 0.f); v1.y = fmaxf(v1.y, 0.f);
            }
            if (res) {
                float2 r0 = *(const float2*)(res + (size_t)r * N + c);
                float2 r1 = *(const float2*)(res + (size_t)(r + 8) * N + c);
                v0.x += r0.x; v0.y += r0.y; v1.x += r1.x; v1.y += r1.y;
            }
            *(float2*)(C + (size_t)r * N + c)       = v0;
            *(float2*)(C + (size_t)(r + 8) * N + c) = v1;
        }
    }
}

// ---------------- Flash attention (fp32), 64-query tile per (b,h) ----------------
__global__ void attn_kernel(const float* __restrict__ Q,
                            const float* __restrict__ Kg,
                            const float* __restrict__ Vg,
                            float* __restrict__ O) {
    extern __shared__ float sm[];
    float* Qt = sm;                  // [64][65]
    float* Kt = sm + 4160;           // [64][65]
    float* Vs = sm + 8320;           // [64][64]
    float* Ss = sm + 12416;          // [64][65]

    int b = blockIdx.z, h = blockIdx.y, qt = blockIdx.x;
    int tid = threadIdx.x;
    int ty = tid >> 4, tx = tid & 15;
    int lr = tid >> 2;
    int c0 = tid & 3;

    {
        size_t grow = (size_t)(b * SEQ + qt * 64 + lr) * DMODEL + h * 64;
        #pragma unroll
        for (int i = 0; i < 4; i++) {
            int cch = c0 + 4 * i;
            float4 v = *(const float4*)(Q + grow + cch * 4);
            Qt[(cch * 4 + 0) * 65 + lr] = v.x * 0.125f;
            Qt[(cch * 4 + 1) * 65 + lr] = v.y * 0.125f;
            Qt[(cch * 4 + 2) * 65 + lr] = v.z * 0.125f;
            Qt[(cch * 4 + 3) * 65 + lr] = v.w * 0.125f;
        }
    }

    float m_i[4], l_i[4], o_acc[4][4];
    #pragma unroll
    for (int i = 0; i < 4; i++) {
        m_i[i] = -1e30f; l_i[i] = 0.f;
        #pragma unroll
        for (int j = 0; j < 4; j++) o_acc[i][j] = 0.f;
    }

    for (int kt = 0; kt < SEQ / 64; kt++) {
        __syncthreads();
        {
            size_t grow = (size_t)(b * SEQ + kt * 64 + lr) * DMODEL + h * 64;
            #pragma unroll
            for (int i = 0; i < 4; i++) {
                int cch = c0 + 4 * i;
                float4 kv = *(const float4*)(Kg + grow + cch * 4);
                Kt[(cch * 4 + 0) * 65 + lr] = kv.x;
                Kt[(cch * 4 + 1) * 65 + lr] = kv.y;
                Kt[(cch * 4 + 2) * 65 + lr] = kv.z;
                Kt[(cch * 4 + 3) * 65 + lr] = kv.w;
                float4 vv = *(const float4*)(Vg + grow + cch * 4);
                *(float4*)&Vs[lr * 64 + cch * 4] = vv;
            }
        }
        __syncthreads();

        float s[4][4];
        #pragma unroll
        for (int i = 0; i < 4; i++)
            #pragma unroll
            for (int j = 0; j < 4; j++) s[i][j] = 0.f;
        #pragma unroll 8
        for (int d = 0; d < 64; d++) {
            float qr[4], kr[4];
            #pragma unroll
            for (int i = 0; i < 4; i++) qr[i] = Qt[d * 65 + ty * 4 + i];
            #pragma unroll
            for (int j = 0; j < 4; j++) kr[j] = Kt[d * 65 + tx * 4 + j];
            #pragma unroll
            for (int i = 0; i < 4; i++)
                #pragma unroll
                for (int j = 0; j < 4; j++) s[i][j] += qr[i] * kr[j];
        }

        #pragma unroll
        for (int i = 0; i < 4; i++) {
            float rm = fmaxf(fmaxf(s[i][0], s[i][1]), fmaxf(s[i][2], s[i][3]));
            #pragma unroll
            for (int o = 8; o >= 1; o >>= 1)
                rm = fmaxf(rm, __shfl_xor_sync(0xFFFFFFFFu, rm, o));
            float mnew  = fmaxf(m_i[i], rm);
            float alpha = __expf(m_i[i] - mnew);
            m_i[i] = mnew;
            float rsum = 0.f;
            #pragma unroll
            for (int j = 0; j < 4; j++) {
                s[i][j] = __expf(s[i][j] - mnew);
                rsum += s[i][j];
            }
            #pragma unroll
            for (int o = 8; o >= 1; o >>= 1)
                rsum += __shfl_xor_sync(0xFFFFFFFFu, rsum, o);
            l_i[i] = l_i[i] * alpha + rsum;
            #pragma unroll
            for (int j = 0; j < 4; j++) o_acc[i][j] *= alpha;
            #pragma unroll
            for (int j = 0; j < 4; j++)
                Ss[(ty * 4 + i) * 65 + tx * 4 + j] = s[i][j];
        }
        __syncthreads();

        #pragma unroll 8
        for (int kk = 0; kk < 64; kk++) {
            float4 vv = *(const float4*)&Vs[kk * 64 + tx * 4];
            float p[4];
            #pragma unroll
            for (int i = 0; i < 4; i++) p[i] = Ss[(ty * 4 + i) * 65 + kk];
            #pragma unroll
            for (int i = 0; i < 4; i++) {
                o_acc[i][0] += p[i] * vv.x;
                o_acc[i][1] += p[i] * vv.y;
                o_acc[i][2] += p[i] * vv.z;
                o_acc[i][3] += p[i] * vv.w;
            }
        }
    }

    #pragma unroll
    for (int i = 0; i < 4; i++) {
        float inv = 1.0f / l_i[i];
        float4 val;
        val.x = o_acc[i][0] * inv;
        val.y = o_acc[i][1] * inv;
        val.z = o_acc[i][2] * inv;
        val.w = o_acc[i][3] * inv;
        size_t idx = (size_t)(b * SEQ + qt * 64 + ty * 4 + i) * DMODEL + h * 64 + tx * 4;
        *(float4*)(O + idx) = val;
    }
}

// ---------------- launch ----------------
extern "C" void kernel_launch(void* const* d_in, const int* in_sizes, int n_in,
                              void* d_out, int out_size) {
    const float* x   = (const float*)d_in[0];
    const float* w_q = (const float*)d_in[1];
    const float* w_k = (const float*)d_in[2];
    const float* w_v = (const float*)d_in[3];
    const float* w_o = (const float*)d_in[4];
    const float* w1  = (const float*)d_in[5];
    const float* b1  = (const float*)d_in[6];
    const float* w2  = (const float*)d_in[7];
    const float* b2  = (const float*)d_in[8];
    const float* g1  = (const float*)d_in[9];
    const float* be1 = (const float*)d_in[10];
    const float* g2  = (const float*)d_in[11];
    const float* be2 = (const float*)d_in[12];
    float* out = (float*)d_out;

    float *ln, *q, *k, *v, *att, *x1, *ff;
    cudaGetSymbolAddress((void**)&ln,  g_ln);
    cudaGetSymbolAddress((void**)&q,   g_q);
    cudaGetSymbolAddress((void**)&k,   g_k);
    cudaGetSymbolAddress((void**)&v,   g_v);
    cudaGetSymbolAddress((void**)&att, g_att);
    cudaGetSymbolAddress((void**)&x1,  g_x1);
    cudaGetSymbolAddress((void**)&ff,  g_ff);

    const int attn_smem = (4160 * 3 + 4096) * (int)sizeof(float);  // 66304 B
    cudaFuncSetAttribute(attn_kernel, cudaFuncAttributeMaxDynamicSharedMemorySize, attn_smem);

    dim3 gProj(DMODEL / BN, ROWS / BM);   // 8 x 32
    dim3 gFF1 (FFDIM / BN, ROWS / BM);    // 32 x 32

    // LN1
    ln_kernel<<<ROWS, 256>>>(x, g1, be1, ln);
    // QKV projections (tensor cores)
    gemm_bf16s_kernel<false><<<gProj, 256>>>(ln, w_q, nullptr, nullptr, q, ROWS, DMODEL, DMODEL);
    gemm_bf16s_kernel<false><<<gProj, 256>>>(ln, w_k, nullptr, nullptr, k, ROWS, DMODEL, DMODEL);
    gemm_bf16s_kernel<false><<<gProj, 256>>>(ln, w_v, nullptr, nullptr, v, ROWS, DMODEL, DMODEL);
    // attention
    attn_kernel<<<dim3(SEQ / 64, NHEAD, 2), 256, attn_smem>>>(q, k, v, att);
    // output projection + residual
    gemm_bf16s_kernel<false><<<gProj, 256>>>(att, w_o, nullptr, x, x1, ROWS, DMODEL, DMODEL);
    // LN2
    ln_kernel<<<ROWS, 256>>>(x1, g2, be2, ln);
    // FFN
    gemm_bf16s_kernel<true ><<<gFF1, 256>>>(ln, w1, b1, nullptr, ff, ROWS, FFDIM, DMODEL);
    gemm_bf16s_kernel<false><<<gProj, 256>>>(ff, w2, b2, x1, out, ROWS, DMODEL, FFDIM);
}

// round 5
// speedup vs baseline: 1.7624x; 1.5967x over previous
#include <cuda_runtime.h>
#include <cuda_bf16.h>
#include <math.h>
#include <stdint.h>

#define DMODEL 1024
#define NHEAD  16
#define FFDIM  4096
#define ROWS   4096      // B*S
#define SEQ    2048
#define LN_EPS 1e-6f

typedef __nv_bfloat16 bf16;

// ---------------- scratch (no allocation allowed) ----------------
__device__ float g_q [ROWS * DMODEL];
__device__ float g_k [ROWS * DMODEL];
__device__ float g_v [ROWS * DMODEL];
__device__ float g_x1[ROWS * DMODEL];

__device__ bf16 g_lnh [ROWS * DMODEL],   g_lnl [ROWS * DMODEL];
__device__ bf16 g_atth[ROWS * DMODEL],   g_attl[ROWS * DMODEL];
__device__ bf16 g_ffh [ROWS * FFDIM],    g_ffl [ROWS * FFDIM];
__device__ bf16 g_wqh [DMODEL * DMODEL], g_wql [DMODEL * DMODEL];
__device__ bf16 g_wkh [DMODEL * DMODEL], g_wkl [DMODEL * DMODEL];
__device__ bf16 g_wvh [DMODEL * DMODEL], g_wvl [DMODEL * DMODEL];
__device__ bf16 g_woh [DMODEL * DMODEL], g_wol [DMODEL * DMODEL];
__device__ bf16 g_w1h [DMODEL * FFDIM],  g_w1l [DMODEL * FFDIM];
__device__ bf16 g_w2h [FFDIM * DMODEL],  g_w2l [FFDIM * DMODEL];

__device__ __forceinline__ void split2(float f, bf16& h, bf16& l) {
    h = __float2bfloat16_rn(f);
    l = __float2bfloat16_rn(f - __bfloat162float(h));
}

// ---------------- LayerNorm -> bf16 hi/lo split output ----------------
__global__ void ln_split_kernel(const float* __restrict__ x,
                                const float* __restrict__ gamma,
                                const float* __restrict__ beta,
                                bf16* __restrict__ oh, bf16* __restrict__ ol) {
    int row = blockIdx.x;
    int t = threadIdx.x;                      // 256 threads, 4 floats each
    const float4* xr = (const float4*)(x + (size_t)row * DMODEL);
    float4 v = xr[t];
    float s  = v.x + v.y + v.z + v.w;
    float ss = v.x * v.x + v.y * v.y + v.z * v.z + v.w * v.w;
    #pragma unroll
    for (int o = 16; o > 0; o >>= 1) {
        s  += __shfl_xor_sync(0xFFFFFFFFu, s,  o);
        ss += __shfl_xor_sync(0xFFFFFFFFu, ss, o);
    }
    __shared__ float rs[8], rss[8];
    int wid = t >> 5, lid = t & 31;
    if (lid == 0) { rs[wid] = s; rss[wid] = ss; }
    __syncthreads();
    s = 0.f; ss = 0.f;
    #pragma unroll
    for (int i = 0; i < 8; i++) { s += rs[i]; ss += rss[i]; }
    float mean = s * (1.0f / DMODEL);
    float var  = (ss - (float)DMODEL * mean * mean) * (1.0f / (DMODEL - 1));
    float inv  = 1.0f / (sqrtf(fmaxf(var, 0.0f)) + LN_EPS);
    const float4 gg = ((const float4*)gamma)[t];
    const float4 bb = ((const float4*)beta)[t];
    float o4[4];
    o4[0] = gg.x * (v.x - mean) * inv + bb.x;
    o4[1] = gg.y * (v.y - mean) * inv + bb.y;
    o4[2] = gg.z * (v.z - mean) * inv + bb.z;
    o4[3] = gg.w * (v.w - mean) * inv + bb.w;
    bf16 hh[4], ll[4];
    #pragma unroll
    for (int j = 0; j < 4; j++) split2(o4[j], hh[j], ll[j]);
    size_t base = (size_t)row * DMODEL + t * 4;
    *(uint2*)(oh + base) = *(uint2*)hh;
    *(uint2*)(ol + base) = *(uint2*)ll;
}

// ---------------- Weight transpose + split: [K,N] fp32 -> [N][K] bf16 hi/lo ----
__global__ void wsplit_tr_kernel(const float* __restrict__ W,
                                 bf16* __restrict__ Th, bf16* __restrict__ Tl,
                                 int K, int N) {
    __shared__ float t[32][33];
    int n0 = blockIdx.x * 32, k0 = blockIdx.y * 32;
    int tx = threadIdx.x, ty = threadIdx.y;   // 32 x 8
    #pragma unroll
    for (int i = 0; i < 4; i++)
        t[ty + 8 * i][tx] = W[(size_t)(k0 + ty + 8 * i) * N + n0 + tx];
    __syncthreads();
    #pragma unroll
    for (int i = 0; i < 4; i++) {
        float f = t[tx][ty + 8 * i];
        bf16 h, l; split2(f, h, l);
        size_t o = (size_t)(n0 + ty + 8 * i) * K + k0 + tx;
        Th[o] = h; Tl[o] = l;
    }
}

// ---------------- Tensor-core GEMM: pre-split bf16 operands, cp.async 2-stage ----
// A(hi/lo): [M][K] bf16 row-major.  B(hi/lo): [N][K] bf16 (k-contiguous).
// C = act(A@B^T_as_stored + bias) + res, fp32 out or bf16 hi/lo split out.
#define BM 128
#define BN 128
#define BK 32
#define SKP 40                      // smem row stride in halves
#define TILE_B (128 * SKP * 2)      // 10240 bytes per tile
#define STAGE_B (4 * TILE_B)        // 40960 bytes per stage

__device__ __forceinline__ void cpa16(uint32_t d, const void* s) {
    asm volatile("cp.async.cg.shared.global [%0], [%1], 16;" :: "r"(d), "l"(s));
}
__device__ __forceinline__ void cpcommit() {
    asm volatile("cp.async.commit_group;");
}
template<int W> __device__ __forceinline__ void cpwait() {
    asm volatile("cp.async.wait_group %0;" :: "n"(W));
}

__device__ __forceinline__ void mma16816(float c[4], const unsigned a[4], const unsigned b[2]) {
    asm volatile(
        "mma.sync.aligned.m16n8k16.row.col.f32.bf16.bf16.f32 "
        "{%0,%1,%2,%3}, {%4,%5,%6,%7}, {%8,%9}, {%0,%1,%2,%3};\n"
        : "+f"(c[0]), "+f"(c[1]), "+f"(c[2]), "+f"(c[3])
        : "r"(a[0]), "r"(a[1]), "r"(a[2]), "r"(a[3]), "r"(b[0]), "r"(b[1]));
}

__device__ __forceinline__ void fill_stage(uint32_t sb,
        const bf16* __restrict__ Agh, const bf16* __restrict__ Agl,
        const bf16* __restrict__ Bgh, const bf16* __restrict__ Bgl,
        int row0, int col0, int k0, int K, int tid) {
    int r  = tid >> 1;                 // 0..127
    int kb = (tid & 1) * 32;           // 0 or 32 bytes within 64B of k-data
    size_t aoff = ((size_t)(row0 + r) * K + k0) * 2 + kb;
    size_t boff = ((size_t)(col0 + r) * K + k0) * 2 + kb;
    uint32_t dst = sb + (uint32_t)r * (SKP * 2) + kb;
    cpa16(dst,                   (const char*)Agh + aoff);
    cpa16(dst + 16,              (const char*)Agh + aoff + 16);
    cpa16(dst + TILE_B,          (const char*)Agl + aoff);
    cpa16(dst + TILE_B + 16,     (const char*)Agl + aoff + 16);
    cpa16(dst + 2 * TILE_B,      (const char*)Bgh + boff);
    cpa16(dst + 2 * TILE_B + 16, (const char*)Bgh + boff + 16);
    cpa16(dst + 3 * TILE_B,      (const char*)Bgl + boff);
    cpa16(dst + 3 * TILE_B + 16, (const char*)Bgl + boff + 16);
}

__device__ __forceinline__ unsigned packbf2(float a, float b) {
    __nv_bfloat162 t;
    t.x = __float2bfloat16_rn(a);
    t.y = __float2bfloat16_rn(b);
    return *(unsigned*)&t;
}
__device__ __forceinline__ unsigned packlo2(float a, float b) {
    __nv_bfloat162 t;
    t.x = __float2bfloat16_rn(a - __bfloat162float(__float2bfloat16_rn(a)));
    t.y = __float2bfloat16_rn(b - __bfloat162float(__float2bfloat16_rn(b)));
    return *(unsigned*)&t;
}

template<bool RELU, bool SPLIT>
__global__ __launch_bounds__(256)
void gemm_mma(const bf16* __restrict__ Agh, const bf16* __restrict__ Agl,
              const bf16* __restrict__ Bgh, const bf16* __restrict__ Bgl,
              const float* __restrict__ bias, const float* __restrict__ res,
              float* __restrict__ C, bf16* __restrict__ Ch, bf16* __restrict__ Cl,
              int M, int N, int K) {
    extern __shared__ bf16 smem[];
    uint32_t sbase = (uint32_t)__cvta_generic_to_shared(smem);
    int tid = threadIdx.x, lane = tid & 31, warp = tid >> 5;
    int g = lane >> 2, tig = lane & 3;
    int m_base = (warp & 1) * 64, n_base = (warp >> 1) * 32;
    int row0 = blockIdx.y * BM, col0 = blockIdx.x * BN;

    float acc[4][4][4];
    #pragma unroll
    for (int mi = 0; mi < 4; mi++)
        #pragma unroll
        for (int ni = 0; ni < 4; ni++)
            #pragma unroll
            for (int r = 0; r < 4; r++) acc[mi][ni][r] = 0.0f;

    int NIT = K >> 5;
    fill_stage(sbase, Agh, Agl, Bgh, Bgl, row0, col0, 0, K, tid);
    cpcommit();

    for (int it = 0; it < NIT; ++it) {
        if (it + 1 < NIT) {
            fill_stage(sbase + ((it + 1) & 1) * STAGE_B, Agh, Agl, Bgh, Bgl,
                       row0, col0, (it + 1) << 5, K, tid);
            cpcommit();
            cpwait<1>();
        } else {
            cpwait<0>();
        }
        __syncthreads();

        const bf16* st  = smem + (it & 1) * (STAGE_B / 2);
        const bf16* Ahs = st;
        const bf16* Als = st + TILE_B / 2;
        const bf16* Bhs = st + 2 * (TILE_B / 2);
        const bf16* Bls = st + 3 * (TILE_B / 2);

        #pragma unroll
        for (int ks = 0; ks < 2; ks++) {
            int kk = ks * 16;
            unsigned a_h[4][4], a_l[4][4], b_h[4][2], b_l[4][2];
            #pragma unroll
            for (int mi = 0; mi < 4; mi++) {
                int r = m_base + mi * 16 + g;
                int base = r * SKP + kk + 2 * tig;
                a_h[mi][0] = *(const unsigned*)(Ahs + base);
                a_h[mi][1] = *(const unsigned*)(Ahs + base + 8 * SKP);
                a_h[mi][2] = *(const unsigned*)(Ahs + base + 8);
                a_h[mi][3] = *(const unsigned*)(Ahs + base + 8 * SKP + 8);
                a_l[mi][0] = *(const unsigned*)(Als + base);
                a_l[mi][1] = *(const unsigned*)(Als + base + 8 * SKP);
                a_l[mi][2] = *(const unsigned*)(Als + base + 8);
                a_l[mi][3] = *(const unsigned*)(Als + base + 8 * SKP + 8);
            }
            #pragma unroll
            for (int ni = 0; ni < 4; ni++) {
                int n = n_base + ni * 8 + g;
                int base = n * SKP + kk + 2 * tig;
                b_h[ni][0] = *(const unsigned*)(Bhs + base);
                b_h[ni][1] = *(const unsigned*)(Bhs + base + 8);
                b_l[ni][0] = *(const unsigned*)(Bls + base);
                b_l[ni][1] = *(const unsigned*)(Bls + base + 8);
            }
            #pragma unroll
            for (int mi = 0; mi < 4; mi++)
                #pragma unroll
                for (int ni = 0; ni < 4; ni++) {
                    mma16816(acc[mi][ni], a_h[mi], b_h[ni]);
                    mma16816(acc[mi][ni], a_h[mi], b_l[ni]);
                    mma16816(acc[mi][ni], a_l[mi], b_h[ni]);
                }
        }
        __syncthreads();
    }

    // ---- epilogue ----
    #pragma unroll
    for (int mi = 0; mi < 4; mi++) {
        #pragma unroll
        for (int ni = 0; ni < 4; ni++) {
            int r = row0 + m_base + mi * 16 + g;
            int c = col0 + n_base + ni * 8 + 2 * tig;
            float2 b2 = make_float2(0.f, 0.f);
            if (bias) b2 = *(const float2*)(bias + c);
            float2 v0, v1;
            v0.x = acc[mi][ni][0] + b2.x; v0.y = acc[mi][ni][1] + b2.y;
            v1.x = acc[mi][ni][2] + b2.x; v1.y = acc[mi][ni][3] + b2.y;
            if (RELU) {
                v0.x = fmaxf(v0.x, 0.f); v0.y = fmaxf(v0.y, 0.f);
                v1.x = fmaxf(v1.x, 0.f); v1.y = fmaxf(v1.y, 0.f);
            }
            if (res) {
                float2 r0 = *(const float2*)(res + (size_t)r * N + c);
                float2 r1 = *(const float2*)(res + (size_t)(r + 8) * N + c);
                v0.x += r0.x; v0.y += r0.y; v1.x += r1.x; v1.y += r1.y;
            }
            if (SPLIT) {
                *(unsigned*)(Ch + (size_t)r * N + c)       = packbf2(v0.x, v0.y);
                *(unsigned*)(Ch + (size_t)(r + 8) * N + c) = packbf2(v1.x, v1.y);
                *(unsigned*)(Cl + (size_t)r * N + c)       = packlo2(v0.x, v0.y);
                *(unsigned*)(Cl + (size_t)(r + 8) * N + c) = packlo2(v1.x, v1.y);
            } else {
                *(float2*)(C + (size_t)r * N + c)       = v0;
                *(float2*)(C + (size_t)(r + 8) * N + c) = v1;
            }
        }
    }
}

// ---------------- Flash attention (fp32) -> bf16 hi/lo split output ----------------
__global__ void attn_kernel(const float* __restrict__ Q,
                            const float* __restrict__ Kg,
                            const float* __restrict__ Vg,
                            bf16* __restrict__ Oh, bf16* __restrict__ Ol) {
    extern __shared__ float sm[];
    float* Qt = sm;                  // [64][65]
    float* Kt = sm + 4160;           // [64][65]
    float* Vs = sm + 8320;           // [64][64]
    float* Ss = sm + 12416;          // [64][65]

    int b = blockIdx.z, h = blockIdx.y, qt = blockIdx.x;
    int tid = threadIdx.x;
    int ty = tid >> 4, tx = tid & 15;
    int lr = tid >> 2;
    int c0 = tid & 3;

    {
        size_t grow = (size_t)(b * SEQ + qt * 64 + lr) * DMODEL + h * 64;
        #pragma unroll
        for (int i = 0; i < 4; i++) {
            int cch = c0 + 4 * i;
            float4 v = *(const float4*)(Q + grow + cch * 4);
            Qt[(cch * 4 + 0) * 65 + lr] = v.x * 0.125f;
            Qt[(cch * 4 + 1) * 65 + lr] = v.y * 0.125f;
            Qt[(cch * 4 + 2) * 65 + lr] = v.z * 0.125f;
            Qt[(cch * 4 + 3) * 65 + lr] = v.w * 0.125f;
        }
    }

    float m_i[4], l_i[4], o_acc[4][4];
    #pragma unroll
    for (int i = 0; i < 4; i++) {
        m_i[i] = -1e30f; l_i[i] = 0.f;
        #pragma unroll
        for (int j = 0; j < 4; j++) o_acc[i][j] = 0.f;
    }

    for (int kt = 0; kt < SEQ / 64; kt++) {
        __syncthreads();
        {
            size_t grow = (size_t)(b * SEQ + kt * 64 + lr) * DMODEL + h * 64;
            #pragma unroll
            for (int i = 0; i < 4; i++) {
                int cch = c0 + 4 * i;
                float4 kv = *(const float4*)(Kg + grow + cch * 4);
                Kt[(cch * 4 + 0) * 65 + lr] = kv.x;
                Kt[(cch * 4 + 1) * 65 + lr] = kv.y;
                Kt[(cch * 4 + 2) * 65 + lr] = kv.z;
                Kt[(cch * 4 + 3) * 65 + lr] = kv.w;
                float4 vv = *(const float4*)(Vg + grow + cch * 4);
                *(float4*)&Vs[lr * 64 + cch * 4] = vv;
            }
        }
        __syncthreads();

        float s[4][4];
        #pragma unroll
        for (int i = 0; i < 4; i++)
            #pragma unroll
            for (int j = 0; j < 4; j++) s[i][j] = 0.f;
        #pragma unroll 8
        for (int d = 0; d < 64; d++) {
            float qr[4], kr[4];
            #pragma unroll
            for (int i = 0; i < 4; i++) qr[i] = Qt[d * 65 + ty * 4 + i];
            #pragma unroll
            for (int j = 0; j < 4; j++) kr[j] = Kt[d * 65 + tx * 4 + j];
            #pragma unroll
            for (int i = 0; i < 4; i++)
                #pragma unroll
                for (int j = 0; j < 4; j++) s[i][j] += qr[i] * kr[j];
        }

        #pragma unroll
        for (int i = 0; i < 4; i++) {
            float rm = fmaxf(fmaxf(s[i][0], s[i][1]), fmaxf(s[i][2], s[i][3]));
            #pragma unroll
            for (int o = 8; o >= 1; o >>= 1)
                rm = fmaxf(rm, __shfl_xor_sync(0xFFFFFFFFu, rm, o));
            float mnew  = fmaxf(m_i[i], rm);
            float alpha = __expf(m_i[i] - mnew);
            m_i[i] = mnew;
            float rsum = 0.f;
            #pragma unroll
            for (int j = 0; j < 4; j++) {
                s[i][j] = __expf(s[i][j] - mnew);
                rsum += s[i][j];
            }
            #pragma unroll
            for (int o = 8; o >= 1; o >>= 1)
                rsum += __shfl_xor_sync(0xFFFFFFFFu, rsum, o);
            l_i[i] = l_i[i] * alpha + rsum;
            #pragma unroll
            for (int j = 0; j < 4; j++) o_acc[i][j] *= alpha;
            #pragma unroll
            for (int j = 0; j < 4; j++)
                Ss[(ty * 4 + i) * 65 + tx * 4 + j] = s[i][j];
        }
        __syncthreads();

        #pragma unroll 8
        for (int kk = 0; kk < 64; kk++) {
            float4 vv = *(const float4*)&Vs[kk * 64 + tx * 4];
            float p[4];
            #pragma unroll
            for (int i = 0; i < 4; i++) p[i] = Ss[(ty * 4 + i) * 65 + kk];
            #pragma unroll
            for (int i = 0; i < 4; i++) {
                o_acc[i][0] += p[i] * vv.x;
                o_acc[i][1] += p[i] * vv.y;
                o_acc[i][2] += p[i] * vv.z;
                o_acc[i][3] += p[i] * vv.w;
            }
        }
    }

    #pragma unroll
    for (int i = 0; i < 4; i++) {
        float inv = 1.0f / l_i[i];
        float o4[4];
        #pragma unroll
        for (int j = 0; j < 4; j++) o4[j] = o_acc[i][j] * inv;
        bf16 hh[4], ll[4];
        #pragma unroll
        for (int j = 0; j < 4; j++) split2(o4[j], hh[j], ll[j]);
        size_t idx = (size_t)(b * SEQ + qt * 64 + ty * 4 + i) * DMODEL + h * 64 + tx * 4;
        *(uint2*)(Oh + idx) = *(uint2*)hh;
        *(uint2*)(Ol + idx) = *(uint2*)ll;
    }
}

// ---------------- launch ----------------
extern "C" void kernel_launch(void* const* d_in, const int* in_sizes, int n_in,
                              void* d_out, int out_size) {
    const float* x   = (const float*)d_in[0];
    const float* w_q = (const float*)d_in[1];
    const float* w_k = (const float*)d_in[2];
    const float* w_v = (const float*)d_in[3];
    const float* w_o = (const float*)d_in[4];
    const float* w1  = (const float*)d_in[5];
    const float* b1  = (const float*)d_in[6];
    const float* w2  = (const float*)d_in[7];
    const float* b2  = (const float*)d_in[8];
    const float* g1  = (const float*)d_in[9];
    const float* be1 = (const float*)d_in[10];
    const float* g2  = (const float*)d_in[11];
    const float* be2 = (const float*)d_in[12];
    float* out = (float*)d_out;

    float *q, *k, *v, *x1;
    bf16 *lnh, *lnl, *atth, *attl, *ffh, *ffl;
    bf16 *wqh, *wql, *wkh, *wkl, *wvh, *wvl, *woh, *wol, *w1h, *w1l, *w2h, *w2l;
    cudaGetSymbolAddress((void**)&q,   g_q);
    cudaGetSymbolAddress((void**)&k,   g_k);
    cudaGetSymbolAddress((void**)&v,   g_v);
    cudaGetSymbolAddress((void**)&x1,  g_x1);
    cudaGetSymbolAddress((void**)&lnh, g_lnh);  cudaGetSymbolAddress((void**)&lnl, g_lnl);
    cudaGetSymbolAddress((void**)&atth,g_atth); cudaGetSymbolAddress((void**)&attl,g_attl);
    cudaGetSymbolAddress((void**)&ffh, g_ffh);  cudaGetSymbolAddress((void**)&ffl, g_ffl);
    cudaGetSymbolAddress((void**)&wqh, g_wqh);  cudaGetSymbolAddress((void**)&wql, g_wql);
    cudaGetSymbolAddress((void**)&wkh, g_wkh);  cudaGetSymbolAddress((void**)&wkl, g_wkl);
    cudaGetSymbolAddress((void**)&wvh, g_wvh);  cudaGetSymbolAddress((void**)&wvl, g_wvl);
    cudaGetSymbolAddress((void**)&woh, g_woh);  cudaGetSymbolAddress((void**)&wol, g_wol);
    cudaGetSymbolAddress((void**)&w1h, g_w1h);  cudaGetSymbolAddress((void**)&w1l, g_w1l);
    cudaGetSymbolAddress((void**)&w2h, g_w2h);  cudaGetSymbolAddress((void**)&w2l, g_w2l);

    const int attn_smem = (4160 * 3 + 4096) * (int)sizeof(float);  // 66304 B
    cudaFuncSetAttribute(attn_kernel, cudaFuncAttributeMaxDynamicSharedMemorySize, attn_smem);
    const int gemm_smem = 2 * STAGE_B;                              // 81920 B
    cudaFuncSetAttribute(gemm_mma<false, false>, cudaFuncAttributeMaxDynamicSharedMemorySize, gemm_smem);
    cudaFuncSetAttribute(gemm_mma<true,  true >, cudaFuncAttributeMaxDynamicSharedMemorySize, gemm_smem);

    dim3 wb(32, 8);
    dim3 gProj(DMODEL / BN, ROWS / BM);   // 8 x 32
    dim3 gFF1 (FFDIM / BN, ROWS / BM);    // 32 x 32

    // weight convert/transpose (cheap, memory-bound)
    wsplit_tr_kernel<<<dim3(DMODEL/32, DMODEL/32), wb>>>(w_q, wqh, wql, DMODEL, DMODEL);
    wsplit_tr_kernel<<<dim3(DMODEL/32, DMODEL/32), wb>>>(w_k, wkh, wkl, DMODEL, DMODEL);
    wsplit_tr_kernel<<<dim3(DMODEL/32, DMODEL/32), wb>>>(w_v, wvh, wvl, DMODEL, DMODEL);
    wsplit_tr_kernel<<<dim3(DMODEL/32, DMODEL/32), wb>>>(w_o, woh, wol, DMODEL, DMODEL);
    wsplit_tr_kernel<<<dim3(FFDIM/32,  DMODEL/32), wb>>>(w1,  w1h, w1l, DMODEL, FFDIM);
    wsplit_tr_kernel<<<dim3(DMODEL/32, FFDIM/32),  wb>>>(w2,  w2h, w2l, FFDIM, DMODEL);

    // LN1 -> split
    ln_split_kernel<<<ROWS, 256>>>(x, g1, be1, lnh, lnl);
    // QKV projections
    gemm_mma<false,false><<<gProj, 256, gemm_smem>>>(lnh, lnl, wqh, wql, nullptr, nullptr, q,  nullptr, nullptr, ROWS, DMODEL, DMODEL);
    gemm_mma<false,false><<<gProj, 256, gemm_smem>>>(lnh, lnl, wkh, wkl, nullptr, nullptr, k,  nullptr, nullptr, ROWS, DMODEL, DMODEL);
    gemm_mma<false,false><<<gProj, 256, gemm_smem>>>(lnh, lnl, wvh, wvl, nullptr, nullptr, v,  nullptr, nullptr, ROWS, DMODEL, DMODEL);
    // attention -> split output
    attn_kernel<<<dim3(SEQ / 64, NHEAD, 2), 256, attn_smem>>>(q, k, v, atth, attl);
    // output projection + residual (fp32 out)
    gemm_mma<false,false><<<gProj, 256, gemm_smem>>>(atth, attl, woh, wol, nullptr, x, x1, nullptr, nullptr, ROWS, DMODEL, DMODEL);
    // LN2 -> split
    ln_split_kernel<<<ROWS, 256>>>(x1, g2, be2, lnh, lnl);
    // FFN
    gemm_mma<true, true ><<<gFF1,  256, gemm_smem>>>(lnh, lnl, w1h, w1l, b1, nullptr, nullptr, ffh, ffl, ROWS, FFDIM, DMODEL);
    gemm_mma<false,false><<<gProj, 256, gemm_smem>>>(ffh, ffl, w2h, w2l, b2, x1, out, nullptr, nullptr, ROWS, DMODEL, FFDIM);
}

// round 6
// speedup vs baseline: 2.4876x; 1.4114x over previous
#include <cuda_runtime.h>
#include <cuda_bf16.h>
#include <math.h>
#include <stdint.h>

#define DMODEL 1024
#define NHEAD  16
#define FFDIM  4096
#define ROWS   4096      // B*S
#define SEQ    2048
#define LN_EPS 1e-6f

typedef __nv_bfloat16 bf16;

// ---------------- scratch (no allocation allowed) ----------------
__device__ float g_x1[ROWS * DMODEL];

__device__ bf16 g_lnh [ROWS * DMODEL],   g_lnl [ROWS * DMODEL];
__device__ bf16 g_qh  [ROWS * DMODEL],   g_ql  [ROWS * DMODEL];
__device__ bf16 g_kh  [ROWS * DMODEL],   g_kl  [ROWS * DMODEL];
__device__ bf16 g_vh  [ROWS * DMODEL],   g_vl  [ROWS * DMODEL];
__device__ bf16 g_vth [ROWS * DMODEL],   g_vtl [ROWS * DMODEL];   // [b,h,d,s]
__device__ bf16 g_atth[ROWS * DMODEL],   g_attl[ROWS * DMODEL];
__device__ bf16 g_ffh [ROWS * FFDIM],    g_ffl [ROWS * FFDIM];
__device__ bf16 g_wqh [DMODEL * DMODEL], g_wql [DMODEL * DMODEL];
__device__ bf16 g_wkh [DMODEL * DMODEL], g_wkl [DMODEL * DMODEL];
__device__ bf16 g_wvh [DMODEL * DMODEL], g_wvl [DMODEL * DMODEL];
__device__ bf16 g_woh [DMODEL * DMODEL], g_wol [DMODEL * DMODEL];
__device__ bf16 g_w1h [DMODEL * FFDIM],  g_w1l [DMODEL * FFDIM];
__device__ bf16 g_w2h [FFDIM * DMODEL],  g_w2l [FFDIM * DMODEL];

__device__ __forceinline__ void split2(float f, bf16& h, bf16& l) {
    h = __float2bfloat16_rn(f);
    l = __float2bfloat16_rn(f - __bfloat162float(h));
}
__device__ __forceinline__ unsigned packbf2(float a, float b) {
    __nv_bfloat162 t;
    t.x = __float2bfloat16_rn(a);
    t.y = __float2bfloat16_rn(b);
    return *(unsigned*)&t;
}
__device__ __forceinline__ unsigned packlo2(float a, float b) {
    __nv_bfloat162 t;
    t.x = __float2bfloat16_rn(a - __bfloat162float(__float2bfloat16_rn(a)));
    t.y = __float2bfloat16_rn(b - __bfloat162float(__float2bfloat16_rn(b)));
    return *(unsigned*)&t;
}

// ---------------- LayerNorm -> bf16 hi/lo split output ----------------
__global__ void ln_split_kernel(const float* __restrict__ x,
                                const float* __restrict__ gamma,
                                const float* __restrict__ beta,
                                bf16* __restrict__ oh, bf16* __restrict__ ol) {
    int row = blockIdx.x;
    int t = threadIdx.x;
    const float4* xr = (const float4*)(x + (size_t)row * DMODEL);
    float4 v = xr[t];
    float s  = v.x + v.y + v.z + v.w;
    float ss = v.x * v.x + v.y * v.y + v.z * v.z + v.w * v.w;
    #pragma unroll
    for (int o = 16; o > 0; o >>= 1) {
        s  += __shfl_xor_sync(0xFFFFFFFFu, s,  o);
        ss += __shfl_xor_sync(0xFFFFFFFFu, ss, o);
    }
    __shared__ float rs[8], rss[8];
    int wid = t >> 5, lid = t & 31;
    if (lid == 0) { rs[wid] = s; rss[wid] = ss; }
    __syncthreads();
    s = 0.f; ss = 0.f;
    #pragma unroll
    for (int i = 0; i < 8; i++) { s += rs[i]; ss += rss[i]; }
    float mean = s * (1.0f / DMODEL);
    float var  = (ss - (float)DMODEL * mean * mean) * (1.0f / (DMODEL - 1));
    float inv  = 1.0f / (sqrtf(fmaxf(var, 0.0f)) + LN_EPS);
    const float4 gg = ((const float4*)gamma)[t];
    const float4 bb = ((const float4*)beta)[t];
    float o4[4];
    o4[0] = gg.x * (v.x - mean) * inv + bb.x;
    o4[1] = gg.y * (v.y - mean) * inv + bb.y;
    o4[2] = gg.z * (v.z - mean) * inv + bb.z;
    o4[3] = gg.w * (v.w - mean) * inv + bb.w;
    bf16 hh[4], ll[4];
    #pragma unroll
    for (int j = 0; j < 4; j++) split2(o4[j], hh[j], ll[j]);
    size_t base = (size_t)row * DMODEL + t * 4;
    *(uint2*)(oh + base) = *(uint2*)hh;
    *(uint2*)(ol + base) = *(uint2*)ll;
}

// ---------------- Weight transpose + split: [K,N] fp32 -> [N][K] bf16 hi/lo ----
__global__ void wsplit_tr_kernel(const float* __restrict__ W,
                                 bf16* __restrict__ Th, bf16* __restrict__ Tl,
                                 int K, int N) {
    __shared__ float t[32][33];
    int n0 = blockIdx.x * 32, k0 = blockIdx.y * 32;
    int tx = threadIdx.x, ty = threadIdx.y;   // 32 x 8
    #pragma unroll
    for (int i = 0; i < 4; i++)
        t[ty + 8 * i][tx] = W[(size_t)(k0 + ty + 8 * i) * N + n0 + tx];
    __syncthreads();
    #pragma unroll
    for (int i = 0; i < 4; i++) {
        float f = t[tx][ty + 8 * i];
        bf16 h, l; split2(f, h, l);
        size_t o = (size_t)(n0 + ty + 8 * i) * K + k0 + tx;
        Th[o] = h; Tl[o] = l;
    }
}

// ---------------- V transpose (bf16): [token][DMODEL] -> [b,h,d,s] ----------------
__global__ void vtr_kernel(const bf16* __restrict__ V, bf16* __restrict__ Vt) {
    __shared__ bf16 t[32][33];
    int s0 = blockIdx.x * 32, d0 = blockIdx.y * 32, z = blockIdx.z;  // z = b*16+h
    int bq = z >> 4, hq = z & 15;
    int tx = threadIdx.x, ty = threadIdx.y;    // 32 x 8
    #pragma unroll
    for (int i = 0; i < 4; i++)
        t[ty + 8 * i][tx] = V[(size_t)(bq * SEQ + s0 + ty + 8 * i) * DMODEL + hq * 64 + d0 + tx];
    __syncthreads();
    #pragma unroll
    for (int i = 0; i < 4; i++)
        Vt[(size_t)(z * 64 + d0 + ty + 8 * i) * SEQ + s0 + tx] = t[tx][ty + 8 * i];
}

// ---------------- common MMA / cp.async helpers ----------------
__device__ __forceinline__ void cpa16(uint32_t d, const void* s) {
    asm volatile("cp.async.cg.shared.global [%0], [%1], 16;" :: "r"(d), "l"(s));
}
__device__ __forceinline__ void cpcommit() {
    asm volatile("cp.async.commit_group;");
}
template<int W> __device__ __forceinline__ void cpwait() {
    asm volatile("cp.async.wait_group %0;" :: "n"(W));
}
__device__ __forceinline__ void mma16816(float c[4], const unsigned a[4], const unsigned b[2]) {
    asm volatile(
        "mma.sync.aligned.m16n8k16.row.col.f32.bf16.bf16.f32 "
        "{%0,%1,%2,%3}, {%4,%5,%6,%7}, {%8,%9}, {%0,%1,%2,%3};\n"
        : "+f"(c[0]), "+f"(c[1]), "+f"(c[2]), "+f"(c[3])
        : "r"(a[0]), "r"(a[1]), "r"(a[2]), "r"(a[3]), "r"(b[0]), "r"(b[1]));
}

// ---------------- Tensor-core GEMM (pre-split bf16, cp.async 2-stage) ----------
#define BM 128
#define BN 128
#define BK 32
#define SKP 40
#define TILE_B (128 * SKP * 2)
#define STAGE_B (4 * TILE_B)

__device__ __forceinline__ void fill_stage(uint32_t sb,
        const bf16* __restrict__ Agh, const bf16* __restrict__ Agl,
        const bf16* __restrict__ Bgh, const bf16* __restrict__ Bgl,
        int row0, int col0, int k0, int K, int tid) {
    int r  = tid >> 1;
    int kb = (tid & 1) * 32;
    size_t aoff = ((size_t)(row0 + r) * K + k0) * 2 + kb;
    size_t boff = ((size_t)(col0 + r) * K + k0) * 2 + kb;
    uint32_t dst = sb + (uint32_t)r * (SKP * 2) + kb;
    cpa16(dst,                   (const char*)Agh + aoff);
    cpa16(dst + 16,              (const char*)Agh + aoff + 16);
    cpa16(dst + TILE_B,          (const char*)Agl + aoff);
    cpa16(dst + TILE_B + 16,     (const char*)Agl + aoff + 16);
    cpa16(dst + 2 * TILE_B,      (const char*)Bgh + boff);
    cpa16(dst + 2 * TILE_B + 16, (const char*)Bgh + boff + 16);
    cpa16(dst + 3 * TILE_B,      (const char*)Bgl + boff);
    cpa16(dst + 3 * TILE_B + 16, (const char*)Bgl + boff + 16);
}

template<bool RELU, bool SPLIT>
__global__ __launch_bounds__(256)
void gemm_mma(const bf16* __restrict__ Agh, const bf16* __restrict__ Agl,
              const bf16* __restrict__ Bgh, const bf16* __restrict__ Bgl,
              const float* __restrict__ bias, const float* __restrict__ res,
              float* __restrict__ C, bf16* __restrict__ Ch, bf16* __restrict__ Cl,
              int M, int N, int K) {
    extern __shared__ bf16 smem[];
    uint32_t sbase = (uint32_t)__cvta_generic_to_shared(smem);
    int tid = threadIdx.x, lane = tid & 31, warp = tid >> 5;
    int g = lane >> 2, tig = lane & 3;
    int m_base = (warp & 1) * 64, n_base = (warp >> 1) * 32;
    int row0 = blockIdx.y * BM, col0 = blockIdx.x * BN;

    float acc[4][4][4];
    #pragma unroll
    for (int mi = 0; mi < 4; mi++)
        #pragma unroll
        for (int ni = 0; ni < 4; ni++)
            #pragma unroll
            for (int r = 0; r < 4; r++) acc[mi][ni][r] = 0.0f;

    int NIT = K >> 5;
    fill_stage(sbase, Agh, Agl, Bgh, Bgl, row0, col0, 0, K, tid);
    cpcommit();

    for (int it = 0; it < NIT; ++it) {
        if (it + 1 < NIT) {
            fill_stage(sbase + ((it + 1) & 1) * STAGE_B, Agh, Agl, Bgh, Bgl,
                       row0, col0, (it + 1) << 5, K, tid);
            cpcommit();
            cpwait<1>();
        } else {
            cpwait<0>();
        }
        __syncthreads();

        const bf16* st  = smem + (it & 1) * (STAGE_B / 2);
        const bf16* Ahs = st;
        const bf16* Als = st + TILE_B / 2;
        const bf16* Bhs = st + 2 * (TILE_B / 2);
        const bf16* Bls = st + 3 * (TILE_B / 2);

        #pragma unroll
        for (int ks = 0; ks < 2; ks++) {
            int kk = ks * 16;
            unsigned a_h[4][4], a_l[4][4], b_h[4][2], b_l[4][2];
            #pragma unroll
            for (int mi = 0; mi < 4; mi++) {
                int r = m_base + mi * 16 + g;
                int base = r * SKP + kk + 2 * tig;
                a_h[mi][0] = *(const unsigned*)(Ahs + base);
                a_h[mi][1] = *(const unsigned*)(Ahs + base + 8 * SKP);
                a_h[mi][2] = *(const unsigned*)(Ahs + base + 8);
                a_h[mi][3] = *(const unsigned*)(Ahs + base + 8 * SKP + 8);
                a_l[mi][0] = *(const unsigned*)(Als + base);
                a_l[mi][1] = *(const unsigned*)(Als + base + 8 * SKP);
                a_l[mi][2] = *(const unsigned*)(Als + base + 8);
                a_l[mi][3] = *(const unsigned*)(Als + base + 8 * SKP + 8);
            }
            #pragma unroll
            for (int ni = 0; ni < 4; ni++) {
                int n = n_base + ni * 8 + g;
                int base = n * SKP + kk + 2 * tig;
                b_h[ni][0] = *(const unsigned*)(Bhs + base);
                b_h[ni][1] = *(const unsigned*)(Bhs + base + 8);
                b_l[ni][0] = *(const unsigned*)(Bls + base);
                b_l[ni][1] = *(const unsigned*)(Bls + base + 8);
            }
            #pragma unroll
            for (int mi = 0; mi < 4; mi++)
                #pragma unroll
                for (int ni = 0; ni < 4; ni++) {
                    mma16816(acc[mi][ni], a_h[mi], b_h[ni]);
                    mma16816(acc[mi][ni], a_h[mi], b_l[ni]);
                    mma16816(acc[mi][ni], a_l[mi], b_h[ni]);
                }
        }
        __syncthreads();
    }

    #pragma unroll
    for (int mi = 0; mi < 4; mi++) {
        #pragma unroll
        for (int ni = 0; ni < 4; ni++) {
            int r = row0 + m_base + mi * 16 + g;
            int c = col0 + n_base + ni * 8 + 2 * tig;
            float2 b2 = make_float2(0.f, 0.f);
            if (bias) b2 = *(const float2*)(bias + c);
            float2 v0, v1;
            v0.x = acc[mi][ni][0] + b2.x; v0.y = acc[mi][ni][1] + b2.y;
            v1.x = acc[mi][ni][2] + b2.x; v1.y = acc[mi][ni][3] + b2.y;
            if (RELU) {
                v0.x = fmaxf(v0.x, 0.f); v0.y = fmaxf(v0.y, 0.f);
                v1.x = fmaxf(v1.x, 0.f); v1.y = fmaxf(v1.y, 0.f);
            }
            if (res) {
                float2 r0 = *(const float2*)(res + (size_t)r * N + c);
                float2 r1 = *(const float2*)(res + (size_t)(r + 8) * N + c);
                v0.x += r0.x; v0.y += r0.y; v1.x += r1.x; v1.y += r1.y;
            }
            if (SPLIT) {
                *(unsigned*)(Ch + (size_t)r * N + c)       = packbf2(v0.x, v0.y);
                *(unsigned*)(Ch + (size_t)(r + 8) * N + c) = packbf2(v1.x, v1.y);
                *(unsigned*)(Cl + (size_t)r * N + c)       = packlo2(v0.x, v0.y);
                *(unsigned*)(Cl + (size_t)(r + 8) * N + c) = packlo2(v1.x, v1.y);
            } else {
                *(float2*)(C + (size_t)r * N + c)       = v0;
                *(float2*)(C + (size_t)(r + 8) * N + c) = v1;
            }
        }
    }
}

// ---------------- MMA flash attention ----------------
// 128-query tile, 8 warps (16 rows each), 64-key tiles, cp.async double buffer.
#define AQT 128
#define ASK 72                    // smem row stride in halves
#define AROWB (ASK * 2)           // 144 bytes
#define ATILE (64 * AROWB)        // 9216 bytes per 64-row operand
#define ASTAGE (4 * ATILE)        // K hi/lo + Vt hi/lo = 36864 bytes

__device__ __forceinline__ void attn_fill(uint32_t sb, int stage,
        const bf16* __restrict__ Kh, const bf16* __restrict__ Kl,
        const bf16* __restrict__ Vth, const bf16* __restrict__ Vtl,
        int b, int h, int kt, int tid) {
    int r  = tid >> 2;                 // 0..63
    int q4 = (tid & 3) * 32;           // byte offset within 128B row
    size_t koff = ((size_t)(b * SEQ + kt * 64 + r) * DMODEL + h * 64) * 2 + q4;
    size_t voff = ((size_t)((b * NHEAD + h) * 64 + r) * SEQ + kt * 64) * 2 + q4;
    uint32_t d = sb + stage * ASTAGE + (uint32_t)r * AROWB + q4;
    cpa16(d,                  (const char*)Kh  + koff);
    cpa16(d + 16,             (const char*)Kh  + koff + 16);
    cpa16(d + ATILE,          (const char*)Kl  + koff);
    cpa16(d + ATILE + 16,     (const char*)Kl  + koff + 16);
    cpa16(d + 2 * ATILE,      (const char*)Vth + voff);
    cpa16(d + 2 * ATILE + 16, (const char*)Vth + voff + 16);
    cpa16(d + 3 * ATILE,      (const char*)Vtl + voff);
    cpa16(d + 3 * ATILE + 16, (const char*)Vtl + voff + 16);
}

__global__ __launch_bounds__(256)
void attn_mma_kernel(const bf16* __restrict__ Qh, const bf16* __restrict__ Ql,
                     const bf16* __restrict__ Kh, const bf16* __restrict__ Kl,
                     const bf16* __restrict__ Vth, const bf16* __restrict__ Vtl,
                     bf16* __restrict__ Oh, bf16* __restrict__ Ol) {
    extern __shared__ char smraw[];
    uint32_t sb = (uint32_t)__cvta_generic_to_shared(smraw);
    int b = blockIdx.z, h = blockIdx.y, qb = blockIdx.x * AQT;
    int tid = threadIdx.x, lane = tid & 31, warp = tid >> 5;
    int g = lane >> 2, tig = lane & 3;

    // ---- stage Q tile (128 x 64) hi/lo into stage-0 area, load fragments ----
    {
        int r = tid >> 1;
        int half = (tid & 1) * 64;
        size_t qoff = ((size_t)(b * SEQ + qb + r) * DMODEL + h * 64) * 2 + half;
        uint32_t d0 = sb + (uint32_t)r * AROWB + half;
        #pragma unroll
        for (int i = 0; i < 4; i++) cpa16(d0 + 16 * i, (const char*)Qh + qoff + 16 * i);
        uint32_t d1 = sb + 2 * ATILE + (uint32_t)r * AROWB + half;
        #pragma unroll
        for (int i = 0; i < 4; i++) cpa16(d1 + 16 * i, (const char*)Ql + qoff + 16 * i);
    }
    cpcommit(); cpwait<0>(); __syncthreads();

    unsigned qfh[4][4], qfl[4][4];
    {
        const bf16* Qs_h = (const bf16*)smraw;
        const bf16* Qs_l = (const bf16*)(smraw + 2 * ATILE);
        int mrow = warp * 16 + g;
        #pragma unroll
        for (int ks = 0; ks < 4; ks++) {
            int base = mrow * ASK + ks * 16 + 2 * tig;
            qfh[ks][0] = *(const unsigned*)(Qs_h + base);
            qfh[ks][1] = *(const unsigned*)(Qs_h + base + 8 * ASK);
            qfh[ks][2] = *(const unsigned*)(Qs_h + base + 8);
            qfh[ks][3] = *(const unsigned*)(Qs_h + base + 8 * ASK + 8);
            qfl[ks][0] = *(const unsigned*)(Qs_l + base);
            qfl[ks][1] = *(const unsigned*)(Qs_l + base + 8 * ASK);
            qfl[ks][2] = *(const unsigned*)(Qs_l + base + 8);
            qfl[ks][3] = *(const unsigned*)(Qs_l + base + 8 * ASK + 8);
        }
    }
    __syncthreads();   // Q smem free before K/V fill reuses it

    float oacc[8][4];
    #pragma unroll
    for (int nf = 0; nf < 8; nf++)
        #pragma unroll
        for (int c = 0; c < 4; c++) oacc[nf][c] = 0.f;
    float mrow[2] = {-1e30f, -1e30f}, lrow[2] = {0.f, 0.f};

    const int NKT = SEQ / 64;   // 32
    attn_fill(sb, 0, Kh, Kl, Vth, Vtl, b, h, 0, tid);
    cpcommit();

    for (int kt = 0; kt < NKT; kt++) {
        if (kt + 1 < NKT) {
            attn_fill(sb, (kt + 1) & 1, Kh, Kl, Vth, Vtl, b, h, kt + 1, tid);
            cpcommit();
            cpwait<1>();
        } else {
            cpwait<0>();
        }
        __syncthreads();

        const bf16* st   = (const bf16*)(smraw + (kt & 1) * ASTAGE);
        const bf16* Ks_h = st;
        const bf16* Ks_l = st + ATILE / 2;
        const bf16* Vs_h = st + 2 * (ATILE / 2);
        const bf16* Vs_l = st + 3 * (ATILE / 2);

        // ---- S = Q @ K^T ----
        float sacc[8][4];
        #pragma unroll
        for (int nf = 0; nf < 8; nf++)
            #pragma unroll
            for (int c = 0; c < 4; c++) sacc[nf][c] = 0.f;
        #pragma unroll
        for (int ks = 0; ks < 4; ks++) {
            #pragma unroll
            for (int nf = 0; nf < 8; nf++) {
                int n = nf * 8 + g;
                int base = n * ASK + ks * 16 + 2 * tig;
                unsigned bh2[2], bl2[2];
                bh2[0] = *(const unsigned*)(Ks_h + base);
                bh2[1] = *(const unsigned*)(Ks_h + base + 8);
                bl2[0] = *(const unsigned*)(Ks_l + base);
                bl2[1] = *(const unsigned*)(Ks_l + base + 8);
                mma16816(sacc[nf], qfh[ks], bh2);
                mma16816(sacc[nf], qfh[ks], bl2);
                mma16816(sacc[nf], qfl[ks], bh2);
            }
        }

        // ---- online softmax on fragments (rows g, g+8 per thread) ----
        #pragma unroll
        for (int nf = 0; nf < 8; nf++)
            #pragma unroll
            for (int c = 0; c < 4; c++) sacc[nf][c] *= 0.125f;

        #pragma unroll
        for (int rr = 0; rr < 2; rr++) {
            float rm = -1e30f;
            #pragma unroll
            for (int nf = 0; nf < 8; nf++)
                rm = fmaxf(rm, fmaxf(sacc[nf][2 * rr], sacc[nf][2 * rr + 1]));
            rm = fmaxf(rm, __shfl_xor_sync(0xFFFFFFFFu, rm, 1));
            rm = fmaxf(rm, __shfl_xor_sync(0xFFFFFFFFu, rm, 2));
            float mn = fmaxf(mrow[rr], rm);
            float al = __expf(mrow[rr] - mn);
            mrow[rr] = mn;
            float rs = 0.f;
            #pragma unroll
            for (int nf = 0; nf < 8; nf++) {
                sacc[nf][2 * rr]     = __expf(sacc[nf][2 * rr]     - mn);
                sacc[nf][2 * rr + 1] = __expf(sacc[nf][2 * rr + 1] - mn);
                rs += sacc[nf][2 * rr] + sacc[nf][2 * rr + 1];
            }
            rs += __shfl_xor_sync(0xFFFFFFFFu, rs, 1);
            rs += __shfl_xor_sync(0xFFFFFFFFu, rs, 2);
            lrow[rr] = lrow[rr] * al + rs;
            #pragma unroll
            for (int nf = 0; nf < 8; nf++) {
                oacc[nf][2 * rr]     *= al;
                oacc[nf][2 * rr + 1] *= al;
            }
        }

        // ---- O += P @ V  (P re-packed C-frag -> A-frag in registers) ----
        #pragma unroll
        for (int ks = 0; ks < 4; ks++) {
            unsigned ph[4], pl[4];
            ph[0] = packbf2(sacc[2 * ks][0],     sacc[2 * ks][1]);
            ph[1] = packbf2(sacc[2 * ks][2],     sacc[2 * ks][3]);
            ph[2] = packbf2(sacc[2 * ks + 1][0], sacc[2 * ks + 1][1]);
            ph[3] = packbf2(sacc[2 * ks + 1][2], sacc[2 * ks + 1][3]);
            pl[0] = packlo2(sacc[2 * ks][0],     sacc[2 * ks][1]);
            pl[1] = packlo2(sacc[2 * ks][2],     sacc[2 * ks][3]);
            pl[2] = packlo2(sacc[2 * ks + 1][0], sacc[2 * ks + 1][1]);
            pl[3] = packlo2(sacc[2 * ks + 1][2], sacc[2 * ks + 1][3]);
            #pragma unroll
            for (int nf = 0; nf < 8; nf++) {
                int n = nf * 8 + g;
                int base = n * ASK + ks * 16 + 2 * tig;
                unsigned vh2[2], vl2[2];
                vh2[0] = *(const unsigned*)(Vs_h + base);
                vh2[1] = *(const unsigned*)(Vs_h + base + 8);
                vl2[0] = *(const unsigned*)(Vs_l + base);
                vl2[1] = *(const unsigned*)(Vs_l + base + 8);
                mma16816(oacc[nf], ph, vh2);
                mma16816(oacc[nf], ph, vl2);
                mma16816(oacc[nf], pl, vh2);
            }
        }
        __syncthreads();
    }

    // ---- epilogue: normalize, split, store ----
    #pragma unroll
    for (int rr = 0; rr < 2; rr++) {
        float inv = 1.0f / lrow[rr];
        size_t r_glob = (size_t)(b * SEQ + qb + warp * 16 + g + rr * 8);
        #pragma unroll
        for (int nf = 0; nf < 8; nf++) {
            int col = h * 64 + nf * 8 + 2 * tig;
            float o0 = oacc[nf][2 * rr] * inv;
            float o1 = oacc[nf][2 * rr + 1] * inv;
            *(unsigned*)(Oh + r_glob * DMODEL + col) = packbf2(o0, o1);
            *(unsigned*)(Ol + r_glob * DMODEL + col) = packlo2(o0, o1);
        }
    }
}

// ---------------- launch ----------------
extern "C" void kernel_launch(void* const* d_in, const int* in_sizes, int n_in,
                              void* d_out, int out_size) {
    const float* x   = (const float*)d_in[0];
    const float* w_q = (const float*)d_in[1];
    const float* w_k = (const float*)d_in[2];
    const float* w_v = (const float*)d_in[3];
    const float* w_o = (const float*)d_in[4];
    const float* w1  = (const float*)d_in[5];
    const float* b1  = (const float*)d_in[6];
    const float* w2  = (const float*)d_in[7];
    const float* b2  = (const float*)d_in[8];
    const float* g1  = (const float*)d_in[9];
    const float* be1 = (const float*)d_in[10];
    const float* g2  = (const float*)d_in[11];
    const float* be2 = (const float*)d_in[12];
    float* out = (float*)d_out;

    float *x1;
    bf16 *lnh, *lnl, *qh, *ql, *kh, *kl, *vh, *vl, *vth, *vtl, *atth, *attl, *ffh, *ffl;
    bf16 *wqh, *wql, *wkh, *wkl, *wvh, *wvl, *woh, *wol, *w1h, *w1l, *w2h, *w2l;
    cudaGetSymbolAddress((void**)&x1,  g_x1);
    cudaGetSymbolAddress((void**)&lnh, g_lnh);  cudaGetSymbolAddress((void**)&lnl, g_lnl);
    cudaGetSymbolAddress((void**)&qh,  g_qh);   cudaGetSymbolAddress((void**)&ql,  g_ql);
    cudaGetSymbolAddress((void**)&kh,  g_kh);   cudaGetSymbolAddress((void**)&kl,  g_kl);
    cudaGetSymbolAddress((void**)&vh,  g_vh);   cudaGetSymbolAddress((void**)&vl,  g_vl);
    cudaGetSymbolAddress((void**)&vth, g_vth);  cudaGetSymbolAddress((void**)&vtl, g_vtl);
    cudaGetSymbolAddress((void**)&atth,g_atth); cudaGetSymbolAddress((void**)&attl,g_attl);
    cudaGetSymbolAddress((void**)&ffh, g_ffh);  cudaGetSymbolAddress((void**)&ffl, g_ffl);
    cudaGetSymbolAddress((void**)&wqh, g_wqh);  cudaGetSymbolAddress((void**)&wql, g_wql);
    cudaGetSymbolAddress((void**)&wkh, g_wkh);  cudaGetSymbolAddress((void**)&wkl, g_wkl);
    cudaGetSymbolAddress((void**)&wvh, g_wvh);  cudaGetSymbolAddress((void**)&wvl, g_wvl);
    cudaGetSymbolAddress((void**)&woh, g_woh);  cudaGetSymbolAddress((void**)&wol, g_wol);
    cudaGetSymbolAddress((void**)&w1h, g_w1h);  cudaGetSymbolAddress((void**)&w1l, g_w1l);
    cudaGetSymbolAddress((void**)&w2h, g_w2h);  cudaGetSymbolAddress((void**)&w2l, g_w2l);

    const int gemm_smem = 2 * STAGE_B;   // 81920 B
    cudaFuncSetAttribute(gemm_mma<false, false>, cudaFuncAttributeMaxDynamicSharedMemorySize, gemm_smem);
    cudaFuncSetAttribute(gemm_mma<false, true >, cudaFuncAttributeMaxDynamicSharedMemorySize, gemm_smem);
    cudaFuncSetAttribute(gemm_mma<true,  true >, cudaFuncAttributeMaxDynamicSharedMemorySize, gemm_smem);
    const int attn_smem = 2 * ASTAGE;    // 73728 B
    cudaFuncSetAttribute(attn_mma_kernel, cudaFuncAttributeMaxDynamicSharedMemorySize, attn_smem);

    dim3 wb(32, 8);
    dim3 gProj(DMODEL / BN, ROWS / BM);
    dim3 gFF1 (FFDIM / BN, ROWS / BM);

    wsplit_tr_kernel<<<dim3(DMODEL/32, DMODEL/32), wb>>>(w_q, wqh, wql, DMODEL, DMODEL);
    wsplit_tr_kernel<<<dim3(DMODEL/32, DMODEL/32), wb>>>(w_k, wkh, wkl, DMODEL, DMODEL);
    wsplit_tr_kernel<<<dim3(DMODEL/32, DMODEL/32), wb>>>(w_v, wvh, wvl, DMODEL, DMODEL);
    wsplit_tr_kernel<<<dim3(DMODEL/32, DMODEL/32), wb>>>(w_o, woh, wol, DMODEL, DMODEL);
    wsplit_tr_kernel<<<dim3(FFDIM/32,  DMODEL/32), wb>>>(w1,  w1h, w1l, DMODEL, FFDIM);
    wsplit_tr_kernel<<<dim3(DMODEL/32, FFDIM/32),  wb>>>(w2,  w2h, w2l, FFDIM, DMODEL);

    // LN1 -> split
    ln_split_kernel<<<ROWS, 256>>>(x, g1, be1, lnh, lnl);
    // QKV projections -> split bf16 outputs
    gemm_mma<false,true><<<gProj, 256, gemm_smem>>>(lnh, lnl, wqh, wql, nullptr, nullptr, nullptr, qh, ql, ROWS, DMODEL, DMODEL);
    gemm_mma<false,true><<<gProj, 256, gemm_smem>>>(lnh, lnl, wkh, wkl, nullptr, nullptr, nullptr, kh, kl, ROWS, DMODEL, DMODEL);
    gemm_mma<false,true><<<gProj, 256, gemm_smem>>>(lnh, lnl, wvh, wvl, nullptr, nullptr, nullptr, vh, vl, ROWS, DMODEL, DMODEL);
    // V transpose to [b,h,d,s]
    vtr_kernel<<<dim3(SEQ/32, 2, 32), wb>>>(vh, vth);
    vtr_kernel<<<dim3(SEQ/32, 2, 32), wb>>>(vl, vtl);
    // MMA attention -> split output
    attn_mma_kernel<<<dim3(SEQ/AQT, NHEAD, 2), 256, attn_smem>>>(qh, ql, kh, kl, vth, vtl, atth, attl);
    // output projection + residual (fp32 out)
    gemm_mma<false,false><<<gProj, 256, gemm_smem>>>(atth, attl, woh, wol, nullptr, x, x1, nullptr, nullptr, ROWS, DMODEL, DMODEL);
    // LN2 -> split
    ln_split_kernel<<<ROWS, 256>>>(x1, g2, be2, lnh, lnl);
    // FFN
    gemm_mma<true, true ><<<gFF1,  256, gemm_smem>>>(lnh, lnl, w1h, w1l, b1, nullptr, nullptr, ffh, ffl, ROWS, FFDIM, DMODEL);
    gemm_mma<false,false><<<gProj, 256, gemm_smem>>>(ffh, ffl, w2h, w2l, b2, x1, out, nullptr, nullptr, ROWS, DMODEL, FFDIM);
}